// round 1
// baseline (speedup 1.0000x reference)
#include <cuda_runtime.h>

// ---------------------------------------------------------------------------
// Problem constants (shapes fixed by the dataset)
// ---------------------------------------------------------------------------
#define P_MAX   32768          // B*N = 8*4096
#define IN_MV   32
#define HALFC   16
#define OUTMV   32
#define IN_S    64
#define OUT_S   64

// hidden scratch between kernel 1 and kernel 2: (P, 32, 16) f32 = 64 MB
static __device__ float g_hidden[(size_t)P_MAX * 32 * 16];

// ---------------------------------------------------------------------------
// Compile-time geometric algebra: blades of Cl(3,0,1), METRIC = (0,1,1,1)
// BLADES order matches the reference:
// (),(0),(1),(2),(3),(01),(02),(03),(12),(13),(23),(012),(013),(023),(123),(0123)
// ---------------------------------------------------------------------------
__host__ __device__ constexpr int ga_popc(int x){ return (x&1)+((x>>1)&1)+((x>>2)&1)+((x>>3)&1); }

__host__ __device__ constexpr int ga_mask(int i){
    return i==0?0: i==1?1: i==2?2: i==3?4: i==4?8: i==5?3: i==6?5: i==7?9:
           i==8?6: i==9?10: i==10?12: i==11?7: i==12?11: i==13?13: i==14?14: 15;
}
__host__ __device__ constexpr int ga_idx(int m){
    return m==0?0: m==1?1: m==2?2: m==4?3: m==8?4: m==3?5: m==5?6: m==9?7:
           m==6?8: m==10?9: m==12?10: m==7?11: m==11?12: m==13?13: m==14?14: 15;
}
__host__ __device__ constexpr int ga_grade(int i){ return ga_popc(ga_mask(i)); }

// sign of reordering concat(a,b) into sorted order (bitmask blades)
__host__ __device__ constexpr int ga_csign(int a, int b){
    int s = 0;
    for (int i = 0; i < 4; ++i) if ((b>>i)&1) s += ga_popc(a >> (i+1));
    return (s&1) ? -1 : 1;
}
__host__ __device__ constexpr int ga_dsign(int b){ return ga_csign(ga_mask(b), 15 ^ ga_mask(b)); }

struct GaTabs {
    signed char gs[16][16]; signed char gi[16][16];   // geometric product: sign, out idx
    signed char js[16][16]; signed char ja[16][16];   // join: sign, out idx
};

__host__ __device__ constexpr GaTabs ga_make(){
    GaTabs t{};
    for (int j = 0; j < 16; ++j)
        for (int k = 0; k < 16; ++k){
            int mj = ga_mask(j), mk = ga_mask(k);
            // geometric product (metric: e0^2 = 0, e1..e3 ^2 = 1)
            if (mj & mk & 1){ t.gs[j][k] = 0; t.gi[j][k] = 0; }
            else { t.gs[j][k] = (signed char)ga_csign(mj, mk); t.gi[j][k] = (signed char)ga_idx(mj ^ mk); }
            // join = D . outer(D. , D.)
            int jm = 15 ^ mj, km = 15 ^ mk;
            if (jm & km){ t.js[j][k] = 0; t.ja[j][k] = 0; }
            else {
                int im = jm ^ km;
                int s = ga_csign(im, 15 ^ im) * ga_csign(jm, km) * ga_dsign(j) * ga_dsign(k);
                t.js[j][k] = (signed char)s;
                t.ja[j][k] = (signed char)ga_idx(15 ^ im);
            }
        }
    return t;
}

// ---------------------------------------------------------------------------
// Kernel 1: four equi_linears -> gp/join bilinears -> hidden (P,32,16)
// Persistent blocks, 512 threads = 16 warps, warp handles 2 positions/pass.
// ---------------------------------------------------------------------------
#define K1_WMV  (32*9*64)         // [i][b][tg64] tg = t*16+o
#define K1_WS   (64*64)           // [s][tg64]
#define K1_STG  1152              // per warp: 2*512 x + 2*64 scalars
#define K1_SMEMF (K1_WMV + K1_WS + 16*K1_STG)

__global__ void __launch_bounds__(512, 1)
k1_hidden(const float* __restrict__ mv, const float* __restrict__ refmv,
          const float* __restrict__ sc,
          const float* __restrict__ wLmv, const float* __restrict__ wLs,
          const float* __restrict__ wRmv, const float* __restrict__ wRs,
          const float* __restrict__ wJLmv, const float* __restrict__ wJLs,
          const float* __restrict__ wJRmv, const float* __restrict__ wJRs,
          int pairsTotal)
{
    extern __shared__ float sm[];
    float* wmvS = sm;                    // K1_WMV
    float* wsS  = sm + K1_WMV;           // K1_WS
    float* stg  = sm + K1_WMV + K1_WS;   // 16 * K1_STG

    const int tid  = threadIdx.x;
    const int warp = tid >> 5;
    const int lane = tid & 31;

    // ---- repack weights into shared: wmvS[(i*9+b)*64 + t*16+o] ----
    {
        const float* wsrc[4] = { wLmv, wRmv, wJLmv, wJRmv };
        for (int idx = tid; idx < K1_WMV; idx += 512){
            int tg = idx & 63, t = tg >> 4, o = tg & 15;
            int ib = idx >> 6, i = ib / 9, b = ib - i*9;
            wmvS[idx] = wsrc[t][(o*32 + i)*9 + b];
        }
        const float* ssrc[4] = { wLs, wRs, wJLs, wJRs };
        for (int idx = tid; idx < K1_WS; idx += 512){
            int tg = idx & 63, t = tg >> 4, o = tg & 15;
            int s  = idx >> 6;
            wsS[idx] = ssrc[t][o*64 + s];
        }
    }
    __syncthreads();

    float* xs = stg + warp * K1_STG;        // [2][512] x then [2][64] scalars
    const int gwarps = gridDim.x * 16;

    for (int pair = blockIdx.x*16 + warp; pair < pairsTotal; pair += gwarps){
        const int p0 = pair * 2;

        __syncwarp();
        // stage x (1024 f) + scalars (128 f), coalesced float4
        {
            float4*       dx = (float4*)xs;
            const float4* sx = (const float4*)(mv + (size_t)p0 * 512);
            #pragma unroll
            for (int q = lane; q < 256; q += 32) dx[q] = sx[q];
            ((float4*)(xs + 1024))[lane] = ((const float4*)(sc + (size_t)p0 * 64))[lane];
        }
        __syncwarp();

        // ---- stage A: 4 equi_linears. lane owns outputs tg0=lane, tg1=lane+32
        //      (t = tg>>4 in {L,R,JL,JR}, o = tg&15), for 2 positions. ----
        float acc[2][2][16];
        #pragma unroll
        for (int p = 0; p < 2; ++p)
            #pragma unroll
            for (int r = 0; r < 2; ++r)
                #pragma unroll
                for (int j = 0; j < 16; ++j) acc[p][r][j] = 0.f;

        #pragma unroll 2
        for (int i = 0; i < 32; ++i){
            const float* wp = wmvS + i * 576;      // 9*64
            float w0[9], w1[9];
            #pragma unroll
            for (int b = 0; b < 9; ++b){ w0[b] = wp[b*64 + lane]; w1[b] = wp[b*64 + 32 + lane]; }
            #pragma unroll
            for (int p = 0; p < 2; ++p){
                const float* xp = xs + p*512 + i*16;
                float xv[16];
                #pragma unroll
                for (int j = 0; j < 16; ++j) xv[j] = xp[j];
                #pragma unroll
                for (int j = 0; j < 16; ++j){
                    acc[p][0][j] += w0[ga_grade(j)] * xv[j];
                    acc[p][1][j] += w1[ga_grade(j)] * xv[j];
                }
                #pragma unroll
                for (int j = 0; j < 16; ++j)
                    if (ga_mask(j) & 1){                      // e0-containing blades
                        const int kk = ga_idx(ga_mask(j) ^ 1);
                        const int bb = 4 + ga_grade(j);
                        acc[p][0][j] += w0[bb] * xv[kk];
                        acc[p][1][j] += w1[bb] * xv[kk];
                    }
            }
        }
        // scalar contribution into component 0
        #pragma unroll 4
        for (int s = 0; s < 64; ++s){
            float a0 = wsS[s*64 + lane], a1 = wsS[s*64 + 32 + lane];
            #pragma unroll
            for (int p = 0; p < 2; ++p){
                float sv = xs[1024 + p*64 + s];
                acc[p][0][0] += a0 * sv;
                acc[p][1][0] += a1 * sv;
            }
        }

        // ---- stage B: bilinears via half-warp exchange ----
        constexpr GaTabs T = ga_make();
        #pragma unroll
        for (int p = 0; p < 2; ++p){
            const int pos = p0 + p;
            const float lam = refmv[(size_t)pos*16 + 15];
            float oth0[16], oth1[16];
            #pragma unroll
            for (int j = 0; j < 16; ++j){
                oth0[j] = __shfl_xor_sync(0xffffffffu, acc[p][0][j], 16);
                oth1[j] = __shfl_xor_sync(0xffffffffu, acc[p][1][j], 16);
            }
            float h[16];
            #pragma unroll
            for (int j = 0; j < 16; ++j) h[j] = 0.f;
            if (lane < 16){
                // gp channel c=lane: left = acc[p][0] (local), right = oth0
                #pragma unroll
                for (int j = 0; j < 16; ++j)
                    #pragma unroll
                    for (int k = 0; k < 16; ++k)
                        if (T.gs[j][k] != 0)
                            h[T.gi[j][k]] += (float)T.gs[j][k] * acc[p][0][j] * oth0[k];
            } else {
                // join channel c=lane-16: jl = oth1, jr = acc[p][1] (local)
                #pragma unroll
                for (int j = 0; j < 16; ++j)
                    #pragma unroll
                    for (int k = 0; k < 16; ++k)
                        if (T.js[j][k] != 0)
                            h[T.ja[j][k]] += (float)T.js[j][k] * oth1[j] * acc[p][1][k];
                #pragma unroll
                for (int j = 0; j < 16; ++j) h[j] *= lam;
            }
            float* hp = g_hidden + ((size_t)pos*32 + lane)*16;
            #pragma unroll
            for (int j = 0; j < 16; j += 4)
                *(float4*)(hp + j) = make_float4(h[j], h[j+1], h[j+2], h[j+3]);
        }
    }
}

// ---------------------------------------------------------------------------
// Kernel 2: out_mv = equi_linear(hidden) ; out_s = W.hidden[:,0] + W.scalars
// ---------------------------------------------------------------------------
#define K2_WOM   (32*9*32)     // [i][b][o32]
#define K2_WS2M  (64*32)       // [s][o32]
#define K2_WM2S  (32*64)       // [c][o64]
#define K2_WS2S  (64*64)       // [s][o64]
#define K2_STG   1152
#define K2_SMEMF (K2_WOM + K2_WS2M + K2_WM2S + K2_WS2S + 16*K2_STG)

__global__ void __launch_bounds__(512, 1)
k2_out(const float* __restrict__ sc,
       const float* __restrict__ wOmv,  const float* __restrict__ wOs2mv,
       const float* __restrict__ wM2s,  const float* __restrict__ wS2s,
       float* __restrict__ out, int pairsTotal, int P)
{
    extern __shared__ float sm[];
    float* womS  = sm;
    float* ws2mS = womS  + K2_WOM;
    float* wm2sS = ws2mS + K2_WS2M;
    float* ws2sS = wm2sS + K2_WM2S;
    float* stg   = ws2sS + K2_WS2S;

    const int tid  = threadIdx.x;
    const int warp = tid >> 5;
    const int lane = tid & 31;

    for (int idx = tid; idx < K2_WOM; idx += 512){
        int o = idx & 31; int ib = idx >> 5; int i = ib / 9, b = ib - i*9;
        womS[idx] = wOmv[(o*32 + i)*9 + b];
    }
    for (int idx = tid; idx < K2_WS2M; idx += 512){
        int o = idx & 31; int s = idx >> 5;
        ws2mS[idx] = wOs2mv[o*64 + s];
    }
    for (int idx = tid; idx < K2_WM2S; idx += 512){
        int o = idx & 63; int c = idx >> 6;
        wm2sS[idx] = wM2s[o*32 + c];
    }
    for (int idx = tid; idx < K2_WS2S; idx += 512){
        int o = idx & 63; int s = idx >> 6;
        ws2sS[idx] = wS2s[o*64 + s];
    }
    __syncthreads();

    float* hs = stg + warp * K2_STG;   // [2][512] hidden then [2][64] scalars
    float* outs = out + (size_t)P * 512;
    const int gwarps = gridDim.x * 16;

    for (int pair = blockIdx.x*16 + warp; pair < pairsTotal; pair += gwarps){
        const int p0 = pair * 2;

        __syncwarp();
        {
            float4*       dh = (float4*)hs;
            const float4* sh = (const float4*)(g_hidden + (size_t)p0 * 512);
            #pragma unroll
            for (int q = lane; q < 256; q += 32) dh[q] = sh[q];
            ((float4*)(hs + 1024))[lane] = ((const float4*)(sc + (size_t)p0 * 64))[lane];
        }
        __syncwarp();

        // out_mv : 32 output channels <-> 32 lanes, 2 positions
        float acc[2][16];
        #pragma unroll
        for (int p = 0; p < 2; ++p)
            #pragma unroll
            for (int j = 0; j < 16; ++j) acc[p][j] = 0.f;

        #pragma unroll 2
        for (int i = 0; i < 32; ++i){
            const float* wp = womS + i * 288;    // 9*32
            float w[9];
            #pragma unroll
            for (int b = 0; b < 9; ++b) w[b] = wp[b*32 + lane];
            #pragma unroll
            for (int p = 0; p < 2; ++p){
                const float* xp = hs + p*512 + i*16;
                float xv[16];
                #pragma unroll
                for (int j = 0; j < 16; ++j) xv[j] = xp[j];
                #pragma unroll
                for (int j = 0; j < 16; ++j) acc[p][j] += w[ga_grade(j)] * xv[j];
                #pragma unroll
                for (int j = 0; j < 16; ++j)
                    if (ga_mask(j) & 1)
                        acc[p][j] += w[4 + ga_grade(j)] * xv[ga_idx(ga_mask(j) ^ 1)];
            }
        }
        #pragma unroll 4
        for (int s = 0; s < 64; ++s){
            float wv = ws2mS[s*32 + lane];
            #pragma unroll
            for (int p = 0; p < 2; ++p) acc[p][0] += wv * hs[1024 + p*64 + s];
        }
        #pragma unroll
        for (int p = 0; p < 2; ++p){
            float* op = out + ((size_t)(p0 + p)*32 + lane)*16;
            #pragma unroll
            for (int j = 0; j < 16; j += 4)
                *(float4*)(op + j) = make_float4(acc[p][j], acc[p][j+1], acc[p][j+2], acc[p][j+3]);
        }

        // out_s : lane handles outputs (lane, lane+32) for both positions
        float as[2][2] = {{0.f,0.f},{0.f,0.f}};
        #pragma unroll 4
        for (int c = 0; c < 32; ++c){
            float wa = wm2sS[c*64 + lane], wb = wm2sS[c*64 + 32 + lane];
            #pragma unroll
            for (int p = 0; p < 2; ++p){
                float hv = hs[p*512 + c*16];
                as[p][0] += wa * hv; as[p][1] += wb * hv;
            }
        }
        #pragma unroll 4
        for (int s = 0; s < 64; ++s){
            float wa = ws2sS[s*64 + lane], wb = ws2sS[s*64 + 32 + lane];
            #pragma unroll
            for (int p = 0; p < 2; ++p){
                float sv = hs[1024 + p*64 + s];
                as[p][0] += wa * sv; as[p][1] += wb * sv;
            }
        }
        #pragma unroll
        for (int p = 0; p < 2; ++p){
            outs[(size_t)(p0 + p)*64 + lane]      = as[p][0];
            outs[(size_t)(p0 + p)*64 + 32 + lane] = as[p][1];
        }
    }
}

// ---------------------------------------------------------------------------
// launch
// ---------------------------------------------------------------------------
extern "C" void kernel_launch(void* const* d_in, const int* in_sizes, int n_in,
                              void* d_out, int out_size)
{
    const float* mv    = (const float*)d_in[0];
    const float* refmv = (const float*)d_in[1];
    const float* sc    = (const float*)d_in[2];
    // d_in[3..5] = basis, gp, jn : tables are regenerated at compile time
    const float* wLmv  = (const float*)d_in[6];
    const float* wLs   = (const float*)d_in[7];
    const float* wRmv  = (const float*)d_in[8];
    const float* wRs   = (const float*)d_in[9];
    const float* wJLmv = (const float*)d_in[10];
    const float* wJLs  = (const float*)d_in[11];
    const float* wJRmv = (const float*)d_in[12];
    const float* wJRs  = (const float*)d_in[13];
    const float* wOmv  = (const float*)d_in[14];
    const float* wOs2m = (const float*)d_in[15];
    const float* wM2s  = (const float*)d_in[16];
    const float* wS2s  = (const float*)d_in[17];
    float* out = (float*)d_out;

    const int P = in_sizes[0] / (IN_MV * 16);     // 32768
    const int pairs = P / 2;

    int sms = 148;
    cudaDeviceGetAttribute(&sms, cudaDevAttrMultiProcessorCount, 0);

    const size_t smem1 = (size_t)K1_SMEMF * sizeof(float);
    const size_t smem2 = (size_t)K2_SMEMF * sizeof(float);
    cudaFuncSetAttribute(k1_hidden, cudaFuncAttributeMaxDynamicSharedMemorySize, (int)smem1);
    cudaFuncSetAttribute(k2_out,    cudaFuncAttributeMaxDynamicSharedMemorySize, (int)smem2);

    k1_hidden<<<sms, 512, smem1>>>(mv, refmv, sc,
                                   wLmv, wLs, wRmv, wRs,
                                   wJLmv, wJLs, wJRmv, wJRs, pairs);
    k2_out<<<sms, 512, smem2>>>(sc, wOmv, wOs2m, wM2s, wS2s, out, pairs, P);
}

// round 2
// speedup vs baseline: 1.2270x; 1.2270x over previous
#include <cuda_runtime.h>

// ---------------------------------------------------------------------------
// Shapes (fixed by dataset): P = 32768 positions, 32 in-ch, 16 blades,
// 64 scalars, hidden 32 ch, out 32 mv-ch + 64 scalars.
// ---------------------------------------------------------------------------
#define NWARP 12
#define NTHR  (NWARP*32)

// ---------------------------------------------------------------------------
// Compile-time geometric algebra for Cl(3,0,1), METRIC=(0,1,1,1).
// Blade order matches reference BLADES list.
// ---------------------------------------------------------------------------
__host__ __device__ constexpr int ga_popc(int x){ return (x&1)+((x>>1)&1)+((x>>2)&1)+((x>>3)&1); }
__host__ __device__ constexpr int ga_mask(int i){
    return i==0?0: i==1?1: i==2?2: i==3?4: i==4?8: i==5?3: i==6?5: i==7?9:
           i==8?6: i==9?10: i==10?12: i==11?7: i==12?11: i==13?13: i==14?14: 15;
}
__host__ __device__ constexpr int ga_idx(int m){
    return m==0?0: m==1?1: m==2?2: m==4?3: m==8?4: m==3?5: m==5?6: m==9?7:
           m==6?8: m==10?9: m==12?10: m==7?11: m==11?12: m==13?13: m==14?14: 15;
}
__host__ __device__ constexpr int ga_grade(int i){ return ga_popc(ga_mask(i)); }
__host__ __device__ constexpr int ga_csign(int a, int b){
    int s = 0;
    for (int i = 0; i < 4; ++i) if ((b>>i)&1) s += ga_popc(a >> (i+1));
    return (s&1) ? -1 : 1;
}
__host__ __device__ constexpr int ga_dsign(int b){ return ga_csign(ga_mask(b), 15 ^ ga_mask(b)); }

struct GaTabs {
    signed char gs[16][16]; signed char gi[16][16];
    signed char js[16][16]; signed char ja[16][16];
};
__host__ __device__ constexpr GaTabs ga_make(){
    GaTabs t{};
    for (int j = 0; j < 16; ++j)
        for (int k = 0; k < 16; ++k){
            int mj = ga_mask(j), mk = ga_mask(k);
            if (mj & mk & 1){ t.gs[j][k] = 0; t.gi[j][k] = 0; }
            else { t.gs[j][k] = (signed char)ga_csign(mj, mk); t.gi[j][k] = (signed char)ga_idx(mj ^ mk); }
            int jm = 15 ^ mj, km = 15 ^ mk;
            if (jm & km){ t.js[j][k] = 0; t.ja[j][k] = 0; }
            else {
                int im = jm ^ km;
                int s = ga_csign(im, 15 ^ im) * ga_csign(jm, km) * ga_dsign(j) * ga_dsign(k);
                t.js[j][k] = (signed char)s;
                t.ja[j][k] = (signed char)ga_idx(15 ^ im);
            }
        }
    return t;
}

// ---------------------------------------------------------------------------
// packed f32x2 helpers
// ---------------------------------------------------------------------------
typedef unsigned long long u64;
__device__ __forceinline__ u64 pk2(float a, float b){ u64 r; asm("mov.b64 %0,{%1,%2};":"=l"(r):"f"(a),"f"(b)); return r; }
__device__ __forceinline__ void unpk2(u64 v, float& a, float& b){ asm("mov.b64 {%0,%1},%2;":"=f"(a),"=f"(b):"l"(v)); }
__device__ __forceinline__ u64 dup2(float a){ u64 r; asm("mov.b64 %0,{%1,%1};":"=l"(r):"f"(a)); return r; }
__device__ __forceinline__ u64 fma2(u64 a, u64 b, u64 c){ u64 d; asm("fma.rn.f32x2 %0,%1,%2,%3;":"=l"(d):"l"(a),"l"(b),"l"(c)); return d; }
__device__ __forceinline__ u64 mul2(u64 a, u64 b){ u64 d; asm("mul.rn.f32x2 %0,%1,%2;":"=l"(d):"l"(a),"l"(b)); return d; }
__device__ __forceinline__ u64 neg2(u64 a){ return a ^ 0x8000000080000000ull; }

// ---------------------------------------------------------------------------
// smem layout (floats)
// ---------------------------------------------------------------------------
#define OFF_WMV   0                      // 32*9*64      = 18432  [i][b][lane*2+r]
#define OFF_WS    (OFF_WMV + 18432)      // 32*32*4      = 4096   [s2][lane][se*2+r]
#define OFF_WOM   (OFF_WS  + 4096)       // 32*9*32      = 9216   [i][b][o]
#define OFF_WS2M  (OFF_WOM + 9216)       // 32*32*2      = 2048   [s2][o][se]
#define OFF_WM2S  (OFF_WS2M+ 2048)       // 16*32*4      = 2048   [c2][lane][ce*2+r]
#define OFF_WS2S  (OFF_WM2S+ 2048)       // 32*32*4      = 4096   [s2][lane][se*2+r]
#define OFF_STG   (OFF_WS2S+ 4096)       // NWARP * 1280
#define STG_PER_WARP 1280                // 32*36 (x/h interleaved) + 128 (scalars)
#define SMEMF (OFF_STG + NWARP*STG_PER_WARP)

__global__ void __launch_bounds__(NTHR, 1)
fused_kernel(const float* __restrict__ mv, const float* __restrict__ refmv,
             const float* __restrict__ sc,
             const float* __restrict__ wLmv, const float* __restrict__ wLs,
             const float* __restrict__ wRmv, const float* __restrict__ wRs,
             const float* __restrict__ wJLmv, const float* __restrict__ wJLs,
             const float* __restrict__ wJRmv, const float* __restrict__ wJRs,
             const float* __restrict__ wOmv,  const float* __restrict__ wOs2mv,
             const float* __restrict__ wM2s,  const float* __restrict__ wS2s,
             float* __restrict__ out, int pairsTotal, int P)
{
    extern __shared__ float sm[];
    const int tid  = threadIdx.x;
    const int warp = tid >> 5;
    const int lane = tid & 31;

    // ---------------- weight repacks ----------------
    {
        const float* wsrc[4] = { wLmv, wRmv, wJLmv, wJRmv };
        for (int idx = tid; idx < 18432; idx += NTHR){
            int r = idx & 1, ln = (idx >> 1) & 31, ib = idx >> 6;
            int b = ib % 9, i = ib / 9;
            int t = (ln < 16) ? r : 2 + r;
            int o = ln & 15;
            sm[OFF_WMV + idx] = wsrc[t][(o*32 + i)*9 + b];
        }
        const float* ssrc[4] = { wLs, wRs, wJLs, wJRs };
        for (int idx = tid; idx < 4096; idx += NTHR){
            int c = idx & 3, ln = (idx >> 2) & 31, s2 = idx >> 7;
            int r = c & 1, se = c >> 1;
            int t = (ln < 16) ? r : 2 + r;
            int o = ln & 15;
            sm[OFF_WS + idx] = ssrc[t][o*64 + s2*2 + se];
        }
        for (int idx = tid; idx < 9216; idx += NTHR){
            int o = idx & 31, ib = idx >> 5, b = ib % 9, i = ib / 9;
            sm[OFF_WOM + idx] = wOmv[(o*32 + i)*9 + b];
        }
        for (int idx = tid; idx < 2048; idx += NTHR){
            int se = idx & 1, o = (idx >> 1) & 31, s2 = idx >> 6;
            sm[OFF_WS2M + idx] = wOs2mv[o*64 + s2*2 + se];
        }
        for (int idx = tid; idx < 2048; idx += NTHR){
            int c4 = idx & 3, ln = (idx >> 2) & 31, c2 = idx >> 7;
            int r = c4 & 1, ce = c4 >> 1;
            sm[OFF_WM2S + idx] = wM2s[(ln + 32*r)*32 + c2*2 + ce];
        }
        for (int idx = tid; idx < 4096; idx += NTHR){
            int c4 = idx & 3, ln = (idx >> 2) & 31, s2 = idx >> 7;
            int r = c4 & 1, se = c4 >> 1;
            sm[OFF_WS2S + idx] = wS2s[(ln + 32*r)*64 + s2*2 + se];
        }
    }
    __syncthreads();

    float* xs = sm + OFF_STG + warp * STG_PER_WARP;   // [i][36] x (then h) interleaved
    float* ss = xs + 1152;                            // [s][2]  scalars interleaved
    float* outs = out + (size_t)P * 512;
    const int gwarps = gridDim.x * NWARP;
    constexpr GaTabs T = ga_make();

    for (int pair = blockIdx.x*NWARP + warp; pair < pairsTotal; pair += gwarps){
        const int p0 = pair * 2;

        __syncwarp();
        // ---------------- stage x interleaved: xs[i*36 + j*2 + p] ----------------
        {
            const float4* s0 = (const float4*)(mv + (size_t)p0 * 512);
            const float4* s1 = s0 + 128;
            #pragma unroll
            for (int k = 0; k < 4; ++k){
                int q = lane + 32*k;
                float4 a = s0[q], b = s1[q];
                int i = q >> 2, j0 = (q & 3) * 4;
                float* dst = xs + i*36 + j0*2;
                *(u64*)(dst + 0) = pk2(a.x, b.x);
                *(u64*)(dst + 2) = pk2(a.y, b.y);
                *(u64*)(dst + 4) = pk2(a.z, b.z);
                *(u64*)(dst + 6) = pk2(a.w, b.w);
            }
            // scalars: 128 floats, interleave [s][p]
            {
                int p = lane >> 4, q = lane & 15;
                float4 v = ((const float4*)(sc + (size_t)(p0 + p)*64))[q];
                ss[(q*4 + 0)*2 + p] = v.x;
                ss[(q*4 + 1)*2 + p] = v.y;
                ss[(q*4 + 2)*2 + p] = v.z;
                ss[(q*4 + 3)*2 + p] = v.w;
            }
        }
        __syncwarp();

        // ---------------- phase 1: paired equi_linears ----------------
        // lane<16: r0 = left[o=lane],  r1 = right[o=lane]   (gp inputs)
        // lane>=16: r0 = jl[o=lane-16], r1 = jr[o=lane-16]  (join inputs)
        u64 acc0[16], acc1[16];
        #pragma unroll
        for (int j = 0; j < 16; ++j){ acc0[j] = 0ull; acc1[j] = 0ull; }

        #pragma unroll 2
        for (int i = 0; i < 32; ++i){
            u64 x2[16];
            {
                const ulonglong2* xr = (const ulonglong2*)(xs + i*36);
                #pragma unroll
                for (int t = 0; t < 8; ++t){ ulonglong2 v = xr[t]; x2[2*t] = v.x; x2[2*t+1] = v.y; }
            }
            const u64* wr = (const u64*)(sm + OFF_WMV + i*576);   // [b][lane] u64
            #pragma unroll
            for (int b = 0; b < 9; ++b){
                float wa, wb; unpk2(wr[b*32 + lane], wa, wb);
                u64 w0 = dup2(wa), w1 = dup2(wb);
                if (b < 5){
                    #pragma unroll
                    for (int j = 0; j < 16; ++j)
                        if (ga_grade(j) == b){
                            acc0[j] = fma2(w0, x2[j], acc0[j]);
                            acc1[j] = fma2(w1, x2[j], acc1[j]);
                        }
                } else {
                    const int g = b - 5;
                    #pragma unroll
                    for (int k = 0; k < 16; ++k)
                        if (!(ga_mask(k) & 1) && ga_grade(k) == g){
                            const int j = ga_idx(ga_mask(k) | 1);
                            acc0[j] = fma2(w0, x2[k], acc0[j]);
                            acc1[j] = fma2(w1, x2[k], acc1[j]);
                        }
                }
            }
        }
        // scalar contribution -> component 0
        #pragma unroll 4
        for (int s2i = 0; s2i < 32; ++s2i){
            float4 w = *(const float4*)(sm + OFF_WS + (s2i*32 + lane)*4);
            ulonglong2 sv = *(const ulonglong2*)(ss + s2i*4);
            acc0[0] = fma2(dup2(w.x), sv.x, acc0[0]);
            acc1[0] = fma2(dup2(w.y), sv.x, acc1[0]);
            acc0[0] = fma2(dup2(w.z), sv.y, acc0[0]);
            acc1[0] = fma2(dup2(w.w), sv.y, acc1[0]);
        }

        // ---------------- bilinears (no shfl: both operands local) ----------------
        u64 h2[16];
        #pragma unroll
        for (int j = 0; j < 16; ++j) h2[j] = 0ull;

        if (lane < 16){
            #pragma unroll
            for (int j = 0; j < 16; ++j)
                #pragma unroll
                for (int k = 0; k < 16; ++k)
                    if (T.gs[j][k] != 0){
                        u64 a = (T.gs[j][k] > 0) ? acc0[j] : neg2(acc0[j]);
                        h2[T.gi[j][k]] = fma2(a, acc1[k], h2[T.gi[j][k]]);
                    }
        } else {
            u64 lam2 = pk2(refmv[(size_t)p0*16 + 15], refmv[(size_t)(p0+1)*16 + 15]);
            #pragma unroll
            for (int j = 0; j < 16; ++j)
                #pragma unroll
                for (int k = 0; k < 16; ++k)
                    if (T.js[j][k] != 0){
                        u64 a = (T.js[j][k] > 0) ? acc0[j] : neg2(acc0[j]);
                        h2[T.ja[j][k]] = fma2(a, acc1[k], h2[T.ja[j][k]]);
                    }
            #pragma unroll
            for (int j = 0; j < 16; ++j) h2[j] = mul2(h2[j], lam2);
        }

        __syncwarp();
        // store hidden channel c=lane into x region (reuse), layout [c][36]
        {
            float* hr = xs + lane*36;
            #pragma unroll
            for (int j = 0; j < 16; ++j) *(u64*)(hr + j*2) = h2[j];
        }
        __syncwarp();

        // ---------------- phase 2: output equi_linear (o = lane) ----------------
        u64 ao[16];
        #pragma unroll
        for (int j = 0; j < 16; ++j) ao[j] = 0ull;

        #pragma unroll 2
        for (int i = 0; i < 32; ++i){
            u64 x2[16];
            {
                const ulonglong2* xr = (const ulonglong2*)(xs + i*36);
                #pragma unroll
                for (int t = 0; t < 8; ++t){ ulonglong2 v = xr[t]; x2[2*t] = v.x; x2[2*t+1] = v.y; }
            }
            const float* wr = sm + OFF_WOM + i*288;
            #pragma unroll
            for (int b = 0; b < 9; ++b){
                u64 w = dup2(wr[b*32 + lane]);
                if (b < 5){
                    #pragma unroll
                    for (int j = 0; j < 16; ++j)
                        if (ga_grade(j) == b) ao[j] = fma2(w, x2[j], ao[j]);
                } else {
                    const int g = b - 5;
                    #pragma unroll
                    for (int k = 0; k < 16; ++k)
                        if (!(ga_mask(k) & 1) && ga_grade(k) == g){
                            const int j = ga_idx(ga_mask(k) | 1);
                            ao[j] = fma2(w, x2[k], ao[j]);
                        }
                }
            }
        }
        // scalars -> component 0
        #pragma unroll 4
        for (int s2i = 0; s2i < 32; ++s2i){
            float wa, wb; unpk2(*(const u64*)(sm + OFF_WS2M + (s2i*32 + lane)*2), wa, wb);
            ulonglong2 sv = *(const ulonglong2*)(ss + s2i*4);
            ao[0] = fma2(dup2(wa), sv.x, ao[0]);
            ao[0] = fma2(dup2(wb), sv.y, ao[0]);
        }
        // store out_mv
        {
            float v0[16], v1[16];
            #pragma unroll
            for (int j = 0; j < 16; ++j) unpk2(ao[j], v0[j], v1[j]);
            float* op0 = out + ((size_t)p0*32 + lane)*16;
            float* op1 = op0 + 512;
            #pragma unroll
            for (int j = 0; j < 16; j += 4){
                *(float4*)(op0 + j) = make_float4(v0[j], v0[j+1], v0[j+2], v0[j+3]);
                *(float4*)(op1 + j) = make_float4(v1[j], v1[j+1], v1[j+2], v1[j+3]);
            }
        }

        // ---------------- out_s: lane owns outputs (lane, lane+32) ----------------
        u64 as0 = 0ull, as1 = 0ull;
        #pragma unroll 4
        for (int c2 = 0; c2 < 16; ++c2){
            float4 w = *(const float4*)(sm + OFF_WM2S + (c2*32 + lane)*4);
            u64 hev = *(const u64*)(xs + (2*c2    )*36);
            u64 hod = *(const u64*)(xs + (2*c2 + 1)*36);
            as0 = fma2(dup2(w.x), hev, as0);
            as1 = fma2(dup2(w.y), hev, as1);
            as0 = fma2(dup2(w.z), hod, as0);
            as1 = fma2(dup2(w.w), hod, as1);
        }
        #pragma unroll 4
        for (int s2i = 0; s2i < 32; ++s2i){
            float4 w = *(const float4*)(sm + OFF_WS2S + (s2i*32 + lane)*4);
            ulonglong2 sv = *(const ulonglong2*)(ss + s2i*4);
            as0 = fma2(dup2(w.x), sv.x, as0);
            as1 = fma2(dup2(w.y), sv.x, as1);
            as0 = fma2(dup2(w.z), sv.y, as0);
            as1 = fma2(dup2(w.w), sv.y, as1);
        }
        {
            float a0, a1, b0, b1;
            unpk2(as0, a0, a1);   // (p0, p1) for output o=lane
            unpk2(as1, b0, b1);   // (p0, p1) for output o=lane+32
            outs[(size_t)p0*64 + lane]            = a0;
            outs[(size_t)(p0+1)*64 + lane]        = a1;
            outs[(size_t)p0*64 + 32 + lane]       = b0;
            outs[(size_t)(p0+1)*64 + 32 + lane]   = b1;
        }
    }
}

// ---------------------------------------------------------------------------
// launch
// ---------------------------------------------------------------------------
extern "C" void kernel_launch(void* const* d_in, const int* in_sizes, int n_in,
                              void* d_out, int out_size)
{
    const float* mv    = (const float*)d_in[0];
    const float* refmv = (const float*)d_in[1];
    const float* sc    = (const float*)d_in[2];
    const float* wLmv  = (const float*)d_in[6];
    const float* wLs   = (const float*)d_in[7];
    const float* wRmv  = (const float*)d_in[8];
    const float* wRs   = (const float*)d_in[9];
    const float* wJLmv = (const float*)d_in[10];
    const float* wJLs  = (const float*)d_in[11];
    const float* wJRmv = (const float*)d_in[12];
    const float* wJRs  = (const float*)d_in[13];
    const float* wOmv  = (const float*)d_in[14];
    const float* wOs2m = (const float*)d_in[15];
    const float* wM2s  = (const float*)d_in[16];
    const float* wS2s  = (const float*)d_in[17];
    float* out = (float*)d_out;

    const int P = in_sizes[0] / (32 * 16);     // 32768
    const int pairs = P / 2;

    int sms = 148;
    cudaDeviceGetAttribute(&sms, cudaDevAttrMultiProcessorCount, 0);

    const size_t smem = (size_t)SMEMF * sizeof(float);
    cudaFuncSetAttribute(fused_kernel, cudaFuncAttributeMaxDynamicSharedMemorySize, (int)smem);

    fused_kernel<<<sms, NTHR, smem>>>(mv, refmv, sc,
                                      wLmv, wLs, wRmv, wRs,
                                      wJLmv, wJLs, wJRmv, wJRs,
                                      wOmv, wOs2m, wM2s, wS2s,
                                      out, pairs, P);
}